// round 16
// baseline (speedup 1.0000x reference)
#include <cuda_runtime.h>
#include <cuda_fp16.h>
#include <cstdint>
#include <cstddef>

#define BATCH   4
#define DIMC    384
#define HEADS   8
#define DHEAD   64
#define INNER   512
#define QKV_CH  1536
#define IMG_H   56
#define IMG_W   56
#define HW      3136
#define NPIX    (BATCH * HW)      // 12544
#define SCALE   0.125f

#define K1      384               // GEMM1: plain fp16, A fused from fp32 x (async)
#define K2      512               // GEMM2: plain fp16

// Scratch (device globals; allocation forbidden)
__device__ __half g_wqkv[(size_t)QKV_CH * DIMC];  // B1: hi
__device__ __half g_wo  [(size_t)DIMC * K2];      // A2: hi of Wo
__device__ __half g_qkvT[(size_t)NPIX * QKV_CH];  // pixel-major q|k|v (fp16)
__device__ __half g_aoT [(size_t)NPIX * INNER];   // B2: hi

// ---------------- PTX helpers (baseline sm_80+ features only) ----------------
__device__ __forceinline__ uint32_t smem_u32(const void* p) {
    uint32_t a;
    asm("{ .reg .u64 t; cvta.to.shared.u64 t, %1; cvt.u32.u64 %0, t; }" : "=r"(a) : "l"(p));
    return a;
}
__device__ __forceinline__ void cp_async16(uint32_t saddr, const void* gptr) {
    asm volatile("cp.async.cg.shared.global [%0], [%1], 16;\n" :: "r"(saddr), "l"(gptr));
}
__device__ __forceinline__ void cp_commit() {
    asm volatile("cp.async.commit_group;\n" ::: "memory");
}
template <int N> __device__ __forceinline__ void cp_wait() {
    asm volatile("cp.async.wait_group %0;\n" :: "n"(N) : "memory");
}
__device__ __forceinline__ void ldsm_x4(uint32_t addr, uint32_t& r0, uint32_t& r1,
                                        uint32_t& r2, uint32_t& r3) {
    asm volatile("ldmatrix.sync.aligned.m8n8.x4.shared.b16 {%0,%1,%2,%3}, [%4];"
                 : "=r"(r0), "=r"(r1), "=r"(r2), "=r"(r3) : "r"(addr));
}
__device__ __forceinline__ void ldsm_x4_t(uint32_t addr, uint32_t& r0, uint32_t& r1,
                                          uint32_t& r2, uint32_t& r3) {
    asm volatile("ldmatrix.sync.aligned.m8n8.x4.trans.shared.b16 {%0,%1,%2,%3}, [%4];"
                 : "=r"(r0), "=r"(r1), "=r"(r2), "=r"(r3) : "r"(addr));
}
__device__ __forceinline__ void mma16816(float* d, const uint32_t* a, const uint32_t* b) {
    asm volatile("mma.sync.aligned.m16n8k16.row.col.f32.f16.f16.f32 "
        "{%0,%1,%2,%3}, {%4,%5,%6,%7}, {%8,%9}, {%0,%1,%2,%3};"
        : "+f"(d[0]), "+f"(d[1]), "+f"(d[2]), "+f"(d[3])
        : "r"(a[0]), "r"(a[1]), "r"(a[2]), "r"(a[3]), "r"(b[0]), "r"(b[1]));
}
__device__ __forceinline__ void sts64(uint32_t addr, uint32_t u0, uint32_t u1) {
    asm volatile("st.shared.v2.u32 [%0], {%1,%2};" :: "r"(addr), "r"(u0), "r"(u1));
}
__device__ __forceinline__ void sts128f(uint32_t addr, float a, float b, float c, float d) {
    asm volatile("st.shared.v4.f32 [%0], {%1,%2,%3,%4};"
                 :: "r"(addr), "f"(a), "f"(b), "f"(c), "f"(d));
}
__device__ __forceinline__ float4 lds128f(uint32_t addr) {
    float4 v;
    asm volatile("ld.shared.v4.f32 {%0,%1,%2,%3}, [%4];"
                 : "=f"(v.x), "=f"(v.y), "=f"(v.z), "=f"(v.w) : "r"(addr));
    return v;
}

// ---------------- weight converts ----------------
__global__ __launch_bounds__(512) void weights_convert(
    const float* __restrict__ Wq, const float* __restrict__ Wkv,
    const float* __restrict__ Wo,
    __half* __restrict__ wqkv, __half* __restrict__ wo)
{
    const int blk = blockIdx.x;
    const int k = threadIdx.x;
    if (blk < QKV_CH) {
        if (k < DIMC) {
            const float w = (blk < INNER) ? Wq[(size_t)blk * DIMC + k]
                                          : Wkv[(size_t)(blk - INNER) * DIMC + k];
            wqkv[(size_t)blk * DIMC + k] = __float2half(w);
        }
    } else {
        const int row = blk - QKV_CH;
        wo[(size_t)row * K2 + k] = __float2half(Wo[(size_t)row * INNER + k]);
    }
}

// ---------------- GEMM1: async fp32 A staging + in-kernel convert ----------------
// D[m=pixel][n=ch] = sum_k x[b][k][hw] * wqkv[n][k]
// Pipeline: group t = cp.async{B(t) fp16, A32(t) fp32}; convert A32(t+1)->A16[(t+1)&1]
// interleaved with mma on A16[t&1]. A16 layout [k][px] fp16 swizzled; ldsm.trans frags.
#define BSTG   32768   // B stage: 256 ch x 128B
#define ASTG32 32768   // A fp32 stage: 64 k x 512B
#define A16S   16384   // A fp16 tile: 64 k x 256B

__device__ __forceinline__ void b_stage_ld(uint32_t sB,
    const __half* __restrict__ Bg, int ldb, int kt, int tid)
{
    #pragma unroll
    for (int i = 0; i < 8; i++) {
        const int idx = tid + i * 256;
        const int row = idx >> 3, j = idx & 7;
        const uint32_t off = (uint32_t)(row * 128 + ((j ^ (row & 7)) * 16));
        cp_async16(sB + off, Bg + (size_t)row * ldb + kt + j * 8);
    }
}

// A fp32 stage: 64 rows (k) x 128 px fp32. Thread chunk = 16B = 4 px.
__device__ __forceinline__ void a32_stage_ld(uint32_t sA32,
    const float* __restrict__ X, const float* __restrict__ xbase,
    int m0, int kt, int tid, bool straddle)
{
    #pragma unroll
    for (int i = 0; i < 8; i++) {
        const int idx = tid + i * 256;
        const int row = idx >> 5, pxg = idx & 31;
        const uint32_t saddr = sA32 + row * 512 + pxg * 16;
        if (!straddle) {
            cp_async16(saddr, xbase + (size_t)(kt + row) * HW + pxg * 4);
        } else {
            float t[4];
            #pragma unroll
            for (int j = 0; j < 4; j++) {
                const int pg = m0 + pxg * 4 + j;
                const int bb = pg / HW;
                const int hw = pg - bb * HW;
                t[j] = X[(size_t)bb * DIMC * HW + (size_t)(kt + row) * HW + hw];
            }
            sts128f(saddr, t[0], t[1], t[2], t[3]);
        }
    }
}

// Convert 2 chunks (i0, i0+1) of this thread's fp32 stage into the fp16 tile.
__device__ __forceinline__ void a_cvt2(uint32_t sA32, uint32_t sA16, int tid, int i0)
{
    #pragma unroll
    for (int ii = 0; ii < 2; ii++) {
        const int idx = tid + (i0 + ii) * 256;
        const int row = idx >> 5, pxg = idx & 31;
        const float4 v = lds128f(sA32 + row * 512 + pxg * 16);
        const __half2 h0 = __floats2half2_rn(v.x, v.y);
        const __half2 h1 = __floats2half2_rn(v.z, v.w);
        const uint32_t addr = sA16 + row * 256 +
            ((((pxg >> 1) ^ (row & 7)) << 4) | ((pxg & 1) << 3));
        sts64(addr, *(const uint32_t*)&h0, *(const uint32_t*)&h1);
    }
}

template <int T>
__global__ __launch_bounds__(256) void hmma_gemm_xa(
    const float* __restrict__ X,
    const __half* __restrict__ B, int ldb,
    __half* __restrict__ C, int ldc)
{
    extern __shared__ char dynraw[];
    const uint32_t smem  = smem_u32(dynraw);
    const uint32_t sBst  = smem;                       // 3 x 32KB
    const uint32_t sA32b = smem + 3 * BSTG;            // 3 x 32KB
    const uint32_t sA16b = smem + 3 * BSTG + 3 * ASTG32; // 2 x 16KB
    const int tid = threadIdx.x;
    const int w = tid >> 5, l = tid & 31;
    const int wm = w >> 2, wn = w & 3;
    const int n0 = blockIdx.x * 256, m0 = blockIdx.y * 128;

    const int b0 = m0 / HW;
    const bool straddle = ((m0 + 127) / HW) != b0;
    const float* xbase = X + (size_t)b0 * DIMC * HW + (m0 - b0 * HW);
    const __half* Bg = B + (size_t)n0 * ldb;

    float acc[4][8][4];
    #pragma unroll
    for (int i = 0; i < 4; i++)
        #pragma unroll
        for (int j = 0; j < 8; j++)
            #pragma unroll
            for (int c = 0; c < 4; c++) acc[i][j][c] = 0.f;

    // A (trans) lane constants
    const int krow_l = (l & 7) + ((l >> 4) & 1) * 8;
    const int mch_l  = ((l >> 3) & 1) * 8;
    const int arowb  = krow_l * 256;
    int amoff[4];
    #pragma unroll
    for (int mi = 0; mi < 4; mi++) {
        const int m_off = wm * 64 + mi * 16 + mch_l;
        amoff[mi] = (((m_off >> 3) ^ (l & 7)) << 4);
    }
    // B lane constants (non-trans, K-major)
    const int brow_l = (l & 7) + ((l >> 4) & 1) * 8;
    const int bcol_l = (l >> 3) & 1;
    int bbase[4], bsw[4];
    #pragma unroll
    for (int jj = 0; jj < 4; jj++) {
        const int nrow = wn * 64 + jj * 16 + brow_l;
        bbase[jj] = nrow * 128;
        bsw[jj]   = nrow & 7;
    }

    // Prologue: groups g0={B0,A32_0}, g1={B1,A32_1}; convert tile 0
    b_stage_ld(sBst, Bg, ldb, 0, tid);
    a32_stage_ld(sA32b, X, xbase, m0, 0, tid, straddle);
    cp_commit();
    b_stage_ld(sBst + BSTG, Bg, ldb, 64, tid);
    a32_stage_ld(sA32b + ASTG32, X, xbase, m0, 64, tid, straddle);
    cp_commit();
    cp_wait<1>();                       // g0 done (own data; no barrier needed)
    a_cvt2(sA32b, sA16b, tid, 0);
    a_cvt2(sA32b, sA16b, tid, 2);
    a_cvt2(sA32b, sA16b, tid, 4);
    a_cvt2(sA32b, sA16b, tid, 6);

    #pragma unroll 1
    for (int t = 0; t < T; t++) {
        if (t + 2 < T) {
            const int s2 = (t + 2) % 3;
            b_stage_ld(sBst + s2 * BSTG, Bg, ldb, (t + 2) * 64, tid);
            a32_stage_ld(sA32b + s2 * ASTG32, X, xbase, m0, (t + 2) * 64, tid, straddle);
        }
        cp_commit();
        cp_wait<1>();                   // group t+1 done -> B(t), A32(t+1) ready
        __syncthreads();                // A16[t&1] + B stage visible to all

        const uint32_t sA16 = sA16b + (t & 1) * A16S;
        const uint32_t sA16n = sA16b + ((t + 1) & 1) * A16S;
        const uint32_t sA32n = sA32b + ((t + 1) % 3) * ASTG32;
        const uint32_t sB = sBst + (t % 3) * BSTG;
        const bool cvt = (t + 1 < T);

        #pragma unroll
        for (int ks = 0; ks < 4; ks++) {
            uint32_t af[4][4];
            #pragma unroll
            for (int mi = 0; mi < 4; mi++)
                ldsm_x4_t(sA16 + arowb + ks * 4096 + amoff[mi],
                          af[mi][0], af[mi][1], af[mi][2], af[mi][3]);
            uint32_t bf[8][2];
            #pragma unroll
            for (int jj = 0; jj < 4; jj++)
                ldsm_x4(sB + bbase[jj] + (((ks * 2 + bcol_l) ^ bsw[jj]) * 16),
                        bf[jj * 2][0], bf[jj * 2][1], bf[jj * 2 + 1][0], bf[jj * 2 + 1][1]);
            #pragma unroll
            for (int i = 0; i < 4; i++)
                #pragma unroll
                for (int j = 0; j < 8; j++)
                    mma16816(acc[i][j], af[i], bf[j]);
            if (cvt) a_cvt2(sA32n, sA16n, tid, ks * 2);
        }
    }

    // Epilogue: lane l holds rows (l>>2) and (l>>2)+8, cols 2*(l&3); fp16 out
    const int r4 = l >> 2;
    const int c2 = (l & 3) * 2;
    #pragma unroll
    for (int i = 0; i < 4; i++) {
        const int row_a = m0 + wm * 64 + i * 16 + r4;
        #pragma unroll
        for (int h = 0; h < 2; h++) {
            const int row = row_a + h * 8;
            #pragma unroll
            for (int j = 0; j < 8; j++) {
                const int col = n0 + wn * 64 + j * 8 + c2;
                const __half2 hv = __floats2half2_rn(acc[i][j][h * 2],
                                                     acc[i][j][h * 2 + 1]);
                *(__half2*)(C + (size_t)row * ldc + col) = hv;
            }
        }
    }
}

// ---------------- GEMM2: plain fp16 both sides (as R15) ----------------
#define STG 49152

__device__ __forceinline__ void stage_ld(uint32_t sA, uint32_t sB,
    const __half* __restrict__ Ag, int lda,
    const __half* __restrict__ Bg, int ldb, int kt, int tid)
{
    #pragma unroll
    for (int i = 0; i < 4; i++) {
        const int idx = tid + i * 256;
        const int row = idx >> 3, j = idx & 7;
        const uint32_t off = (uint32_t)(row * 128 + ((j ^ (row & 7)) * 16));
        cp_async16(sA + off, Ag + (size_t)row * lda + kt + j * 8);
    }
    #pragma unroll
    for (int i = 0; i < 8; i++) {
        const int idx = tid + i * 256;
        const int row = idx >> 3, j = idx & 7;
        const uint32_t off = (uint32_t)(row * 128 + ((j ^ (row & 7)) * 16));
        cp_async16(sB + off, Bg + (size_t)row * ldb + kt + j * 8);
    }
}

template <int T>
__global__ __launch_bounds__(256) void hmma_gemm(
    const __half* __restrict__ A, int lda,
    const __half* __restrict__ B, int ldb,
    const float* __restrict__ bias, float* __restrict__ C)
{
    extern __shared__ char dynraw[];
    const uint32_t smem = smem_u32(dynraw);
    const int tid = threadIdx.x;
    const int w = tid >> 5, l = tid & 31;
    const int wm = w >> 2, wn = w & 3;
    const int n0 = blockIdx.x * 256, m0 = blockIdx.y * 128;

    const __half* Ag = A + (size_t)m0 * lda;
    const __half* Bg = B + (size_t)n0 * ldb;

    float acc[4][8][4];
    #pragma unroll
    for (int i = 0; i < 4; i++)
        #pragma unroll
        for (int j = 0; j < 8; j++)
            #pragma unroll
            for (int c = 0; c < 4; c++) acc[i][j][c] = 0.f;

    const int arow_l = (l & 7) + ((l >> 3) & 1) * 8;
    const int acol_l = (l >> 4) & 1;
    const int brow_l = (l & 7) + ((l >> 4) & 1) * 8;
    const int bcol_l = (l >> 3) & 1;

    int abase[4], asw[4];
    #pragma unroll
    for (int i = 0; i < 4; i++) {
        const int mrow = wm * 64 + i * 16 + arow_l;
        abase[i] = mrow * 128;
        asw[i]   = mrow & 7;
    }
    int bbase[4], bsw[4];
    #pragma unroll
    for (int jj = 0; jj < 4; jj++) {
        const int nrow = wn * 64 + jj * 16 + brow_l;
        bbase[jj] = nrow * 128;
        bsw[jj]   = nrow & 7;
    }

    const int ks0 = ((w >> 2) & 1) << 1;

    stage_ld(smem,       smem + 16384,       Ag, lda, Bg, ldb, 0,  tid); cp_commit();
    stage_ld(smem + STG, smem + STG + 16384, Ag, lda, Bg, ldb, 64, tid); cp_commit();

    #pragma unroll 1
    for (int t = 0; t < T; t++) {
        cp_wait<1>();
        __syncthreads();
        if (t + 2 < T) {
            const int s2 = (t + 2) % 3;
            stage_ld(smem + s2 * STG, smem + s2 * STG + 16384,
                     Ag, lda, Bg, ldb, (t + 2) * 64, tid);
        }
        cp_commit();

        const uint32_t sA = smem + (t % 3) * STG;
        const uint32_t sB = sA + 16384;
        #pragma unroll
        for (int kss = 0; kss < 4; kss++) {
            const int ks = (kss + ks0) & 3;
            uint32_t af[4][4];
            #pragma unroll
            for (int i = 0; i < 4; i++)
                ldsm_x4(sA + abase[i] + (((ks * 2 + acol_l) ^ asw[i]) * 16),
                        af[i][0], af[i][1], af[i][2], af[i][3]);
            uint32_t bf[8][2];
            #pragma unroll
            for (int jj = 0; jj < 4; jj++)
                ldsm_x4(sB + bbase[jj] + (((ks * 2 + bcol_l) ^ bsw[jj]) * 16),
                        bf[jj * 2][0], bf[jj * 2][1], bf[jj * 2 + 1][0], bf[jj * 2 + 1][1]);
            #pragma unroll
            for (int i = 0; i < 4; i++)
                #pragma unroll
                for (int j = 0; j < 8; j++)
                    mma16816(acc[i][j], af[i], bf[j]);
        }
    }

    const int r4 = l >> 2;
    const int c2 = (l & 3) * 2;
    #pragma unroll
    for (int i = 0; i < 4; i++) {
        const int row_a = m0 + wm * 64 + i * 16 + r4;
        #pragma unroll
        for (int h = 0; h < 2; h++) {
            const int row = row_a + h * 8;
            const float bv = bias[row];
            #pragma unroll
            for (int j = 0; j < 8; j++) {
                const int col = n0 + wn * 64 + j * 8 + c2;
                const int bb = col / HW;
                const int hw = col - bb * HW;
                float2 v = make_float2(acc[i][j][h * 2] + bv,
                                       acc[i][j][h * 2 + 1] + bv);
                *(float2*)(C + ((size_t)bb * DIMC + row) * HW + hw) = v;
            }
        }
    }
}

// ---------------- attention: warp per (pixel, head-pair), fp16 qkv (R11) ----------------
__device__ __forceinline__ float4 ld_h4(const __half* p) {
    const uint2 raw = *(const uint2*)p;
    const float2 a = __half22float2(*(const __half2*)&raw.x);
    const float2 b = __half22float2(*(const __half2*)&raw.y);
    return make_float4(a.x, a.y, b.x, b.y);
}

__global__ __launch_bounds__(256) void attn_kernel(
    const __half* __restrict__ qkvT, __half* __restrict__ aoT)
{
    const int w  = threadIdx.x >> 5;
    const int l  = threadIdx.x & 31;
    const int x  = blockIdx.x * 2 + (w >> 2);
    const int y  = blockIdx.y;
    const int b  = blockIdx.z;
    const int hp = w & 3;
    const int chb = hp * 128 + l * 4;

    const __half* base = qkvT + (size_t)(b * HW + y * IMG_W + x) * QKV_CH;
    const float4 q = ld_h4(base + chb);

    const bool interior = (x >= 1) && (x <= IMG_W - 2) && (y >= 1) && (y <= IMG_H - 2);

    float dots[9];
    if (interior) {
        #pragma unroll
        for (int r = 0; r < 3; r++) {
            const __half* krow = base + ((r - 1) * IMG_W - 1) * QKV_CH + INNER + chb;
            #pragma unroll
            for (int c = 0; c < 3; c++) {
                const float4 kk = ld_h4(krow + c * QKV_CH);
                dots[r * 3 + c] = fmaf(q.x, kk.x,
                                  fmaf(q.y, kk.y,
                                  fmaf(q.z, kk.z, q.w * kk.w)));
            }
        }
    } else {
        #pragma unroll
        for (int t = 0; t < 9; t++) {
            const int yy = y + t / 3 - 1;
            const int xx = x + t % 3 - 1;
            float d = 0.f;
            if (yy >= 0 && yy < IMG_H && xx >= 0 && xx < IMG_W) {
                const float4 kk = ld_h4(
                    qkvT + (size_t)(b * HW + yy * IMG_W + xx) * QKV_CH + INNER + chb);
                d = fmaf(q.x, kk.x, fmaf(q.y, kk.y, fmaf(q.z, kk.z, q.w * kk.w)));
            }
            dots[t] = d;
        }
    }

    #pragma unroll
    for (int off = 8; off; off >>= 1)
        #pragma unroll
        for (int t = 0; t < 9; t++)
            dots[t] += __shfl_xor_sync(0xFFFFFFFFu, dots[t], off);

    float m = -1e30f;
    #pragma unroll
    for (int t = 0; t < 9; t++) { dots[t] *= SCALE; m = fmaxf(m, dots[t]); }
    float wgt[9], s = 0.f;
    #pragma unroll
    for (int t = 0; t < 9; t++) { wgt[t] = __expf(dots[t] - m); s += wgt[t]; }
    const float inv = 1.f / s;
    #pragma unroll
    for (int t = 0; t < 9; t++) wgt[t] *= inv;

    float4 o = make_float4(0.f, 0.f, 0.f, 0.f);
    if (interior) {
        #pragma unroll
        for (int r = 0; r < 3; r++) {
            const __half* vrow = base + ((r - 1) * IMG_W - 1) * QKV_CH + 2 * INNER + chb;
            #pragma unroll
            for (int c = 0; c < 3; c++) {
                const float4 vv = ld_h4(vrow + c * QKV_CH);
                const float wt = wgt[r * 3 + c];
                o.x = fmaf(wt, vv.x, o.x);
                o.y = fmaf(wt, vv.y, o.y);
                o.z = fmaf(wt, vv.z, o.z);
                o.w = fmaf(wt, vv.w, o.w);
            }
        }
    } else {
        #pragma unroll
        for (int t = 0; t < 9; t++) {
            const int yy = y + t / 3 - 1;
            const int xx = x + t % 3 - 1;
            if (yy >= 0 && yy < IMG_H && xx >= 0 && xx < IMG_W) {
                const float4 vv = ld_h4(
                    qkvT + (size_t)(b * HW + yy * IMG_W + xx) * QKV_CH + 2 * INNER + chb);
                const float wt = wgt[t];
                o.x = fmaf(wt, vv.x, o.x);
                o.y = fmaf(wt, vv.y, o.y);
                o.z = fmaf(wt, vv.z, o.z);
                o.w = fmaf(wt, vv.w, o.w);
            }
        }
    }

    __half2 p0 = __floats2half2_rn(o.x, o.y);
    __half2 p1 = __floats2half2_rn(o.z, o.w);
    __half2* dst = (__half2*)(aoT + (size_t)(b * HW + y * IMG_W + x) * INNER + chb);
    dst[0] = p0;
    dst[1] = p1;
}

// ---------------- launch ----------------
extern "C" void kernel_launch(void* const* d_in, const int* in_sizes, int n_in,
                              void* d_out, int out_size)
{
    const float* x   = (const float*)d_in[0];
    const float* Wq  = (const float*)d_in[1];
    const float* Wkv = (const float*)d_in[2];
    const float* Wo  = (const float*)d_in[3];
    const float* bo  = (const float*)d_in[4];
    float* out = (float*)d_out;

    __half *wqkv, *wo, *qkvT, *aoT;
    cudaGetSymbolAddress((void**)&wqkv, g_wqkv);
    cudaGetSymbolAddress((void**)&wo,   g_wo);
    cudaGetSymbolAddress((void**)&qkvT, g_qkvT);
    cudaGetSymbolAddress((void**)&aoT,  g_aoT);

    const int g1_smem = 3 * BSTG + 3 * ASTG32 + 2 * A16S;  // 224 KB
    const int g2_smem = 3 * STG;                           // 144 KB
    cudaFuncSetAttribute((const void*)hmma_gemm_xa<K1 / 64>,
                         cudaFuncAttributeMaxDynamicSharedMemorySize, g1_smem);
    cudaFuncSetAttribute((const void*)hmma_gemm<K2 / 64>,
                         cudaFuncAttributeMaxDynamicSharedMemorySize, g2_smem);

    // 0) weight converts only
    weights_convert<<<QKV_CH + DIMC, 512>>>(Wq, Wkv, Wo, wqkv, wo);

    // 1) qkv projection: D[p][ch] fp16, M=12544, N=1536, K=384, A async-fused from x
    hmma_gemm_xa<K1 / 64><<<dim3(QKV_CH / 256, NPIX / 128), 256, g1_smem>>>(
        x, wqkv, DIMC, qkvT, QKV_CH);

    // 2) neighborhood attention (warp per pixel-head-pair, fp16 qkv)
    attn_kernel<<<dim3(IMG_W / 2, IMG_H, BATCH), 256>>>(qkvT, aoT);

    // 3) out projection: D[ch][p] -> out (channel-major) + bias, K=512
    hmma_gemm<K2 / 64><<<dim3(NPIX / 256, DIMC / 128), 256, g2_smem>>>(
        wo, K2, aoT, INNER, bo, out);
}

// round 17
// speedup vs baseline: 1.1035x; 1.1035x over previous
#include <cuda_runtime.h>
#include <cuda_fp16.h>
#include <cstdint>
#include <cstddef>

#define BATCH   4
#define DIMC    384
#define HEADS   8
#define DHEAD   64
#define INNER   512
#define QKV_CH  1536
#define IMG_H   56
#define IMG_W   56
#define HW      3136
#define NPIX    (BATCH * HW)      // 12544
#define SCALE   0.125f

#define K1      384               // GEMM1: plain fp16, A fused from fp32 x
#define K2      512               // GEMM2: plain fp16

// Scratch (device globals; allocation forbidden)
__device__ __half g_wqkv[(size_t)QKV_CH * DIMC];  // B1: hi
__device__ __half g_wo  [(size_t)DIMC * K2];      // A2: hi of Wo
__device__ __half g_qkvT[(size_t)NPIX * QKV_CH];  // pixel-major q|k|v (fp16)
__device__ __half g_aoT [(size_t)NPIX * INNER];   // B2: hi

// ---------------- PTX helpers (baseline sm_80+ features only) ----------------
__device__ __forceinline__ uint32_t smem_u32(const void* p) {
    uint32_t a;
    asm("{ .reg .u64 t; cvta.to.shared.u64 t, %1; cvt.u32.u64 %0, t; }" : "=r"(a) : "l"(p));
    return a;
}
__device__ __forceinline__ void cp_async16(uint32_t saddr, const void* gptr) {
    asm volatile("cp.async.cg.shared.global [%0], [%1], 16;\n" :: "r"(saddr), "l"(gptr));
}
__device__ __forceinline__ void cp_commit() {
    asm volatile("cp.async.commit_group;\n" ::: "memory");
}
template <int N> __device__ __forceinline__ void cp_wait() {
    asm volatile("cp.async.wait_group %0;\n" :: "n"(N) : "memory");
}
__device__ __forceinline__ void ldsm_x4(uint32_t addr, uint32_t& r0, uint32_t& r1,
                                        uint32_t& r2, uint32_t& r3) {
    asm volatile("ldmatrix.sync.aligned.m8n8.x4.shared.b16 {%0,%1,%2,%3}, [%4];"
                 : "=r"(r0), "=r"(r1), "=r"(r2), "=r"(r3) : "r"(addr));
}
__device__ __forceinline__ void ldsm_x4_t(uint32_t addr, uint32_t& r0, uint32_t& r1,
                                          uint32_t& r2, uint32_t& r3) {
    asm volatile("ldmatrix.sync.aligned.m8n8.x4.trans.shared.b16 {%0,%1,%2,%3}, [%4];"
                 : "=r"(r0), "=r"(r1), "=r"(r2), "=r"(r3) : "r"(addr));
}
__device__ __forceinline__ void mma16816(float* d, const uint32_t* a, const uint32_t* b) {
    asm volatile("mma.sync.aligned.m16n8k16.row.col.f32.f16.f16.f32 "
        "{%0,%1,%2,%3}, {%4,%5,%6,%7}, {%8,%9}, {%0,%1,%2,%3};"
        : "+f"(d[0]), "+f"(d[1]), "+f"(d[2]), "+f"(d[3])
        : "r"(a[0]), "r"(a[1]), "r"(a[2]), "r"(a[3]), "r"(b[0]), "r"(b[1]));
}
__device__ __forceinline__ void sts64(uint32_t addr, uint32_t u0, uint32_t u1) {
    asm volatile("st.shared.v2.u32 [%0], {%1,%2};" :: "r"(addr), "r"(u0), "r"(u1));
}

// ---------------- weight converts ----------------
__global__ __launch_bounds__(512) void weights_convert(
    const float* __restrict__ Wq, const float* __restrict__ Wkv,
    const float* __restrict__ Wo,
    __half* __restrict__ wqkv, __half* __restrict__ wo)
{
    const int blk = blockIdx.x;
    const int k = threadIdx.x;
    if (blk < QKV_CH) {
        if (k < DIMC) {
            const float w = (blk < INNER) ? Wq[(size_t)blk * DIMC + k]
                                          : Wkv[(size_t)(blk - INNER) * DIMC + k];
            wqkv[(size_t)blk * DIMC + k] = __float2half(w);
        }
    } else {
        const int row = blk - QKV_CH;
        wo[(size_t)row * K2 + k] = __float2half(Wo[(size_t)row * INNER + k]);
    }
}

// ---------------- GEMM1: fused transpose+convert A (R15 version) ----------------
#define BSTG 32768
#define ASTG 16384

__device__ __forceinline__ void b_stage_ld(uint32_t sB,
    const __half* __restrict__ Bg, int ldb, int kt, int tid)
{
    #pragma unroll
    for (int i = 0; i < 8; i++) {
        const int idx = tid + i * 256;
        const int row = idx >> 3, j = idx & 7;
        const uint32_t off = (uint32_t)(row * 128 + ((j ^ (row & 7)) * 16));
        cp_async16(sB + off, Bg + (size_t)row * ldb + kt + j * 8);
    }
}

__device__ __forceinline__ void a_ldg(float4 pf[4], const float* __restrict__ xbase,
    const float* __restrict__ X, int m0, int kt, int tid, int half, bool straddle)
{
    #pragma unroll
    for (int i = 0; i < 4; i++) {
        const int idx = tid + (half * 4 + i) * 256;
        const int c = idx >> 5, pxg = idx & 31;
        if (!straddle) {
            pf[i] = *(const float4*)(xbase + (size_t)(kt + c) * HW + pxg * 4);
        } else {
            float t[4];
            #pragma unroll
            for (int j = 0; j < 4; j++) {
                const int pg = m0 + pxg * 4 + j;
                const int bb = pg / HW;
                const int hw = pg - bb * HW;
                t[j] = X[(size_t)bb * DIMC * HW + (size_t)(kt + c) * HW + hw];
            }
            pf[i] = make_float4(t[0], t[1], t[2], t[3]);
        }
    }
}

__device__ __forceinline__ void a_sts(uint32_t sA, const float4 pf[4], int tid, int half)
{
    #pragma unroll
    for (int i = 0; i < 4; i++) {
        const int idx = tid + (half * 4 + i) * 256;
        const int c = idx >> 5, pxg = idx & 31;
        const uint32_t addr = sA + c * 256 +
            ((((pxg >> 1) ^ (c & 7)) << 4) | ((pxg & 1) << 3));
        const __half2 h0 = __floats2half2_rn(pf[i].x, pf[i].y);
        const __half2 h1 = __floats2half2_rn(pf[i].z, pf[i].w);
        sts64(addr, *(const uint32_t*)&h0, *(const uint32_t*)&h1);
    }
}

template <int T>
__global__ __launch_bounds__(256) void hmma_gemm_xa(
    const float* __restrict__ X,
    const __half* __restrict__ B, int ldb,
    __half* __restrict__ C, int ldc)
{
    extern __shared__ char dynraw[];
    const uint32_t smem = smem_u32(dynraw);
    const uint32_t sBst = smem;                 // 3 x 32KB
    const uint32_t sAbuf = smem + 3 * BSTG;     // 2 x 16KB
    const int tid = threadIdx.x;
    const int w = tid >> 5, l = tid & 31;
    const int wm = w >> 2, wn = w & 3;
    const int n0 = blockIdx.x * 256, m0 = blockIdx.y * 128;

    const int b0 = m0 / HW;
    const bool straddle = ((m0 + 127) / HW) != b0;
    const float* xbase = X + (size_t)b0 * DIMC * HW + (m0 - b0 * HW);
    const __half* Bg = B + (size_t)n0 * ldb;

    float acc[4][8][4];
    #pragma unroll
    for (int i = 0; i < 4; i++)
        #pragma unroll
        for (int j = 0; j < 8; j++)
            #pragma unroll
            for (int c = 0; c < 4; c++) acc[i][j][c] = 0.f;

    const int krow_l = (l & 7) + ((l >> 4) & 1) * 8;
    const int mch_l  = ((l >> 3) & 1) * 8;
    const int arowb  = krow_l * 256;
    int amoff[4];
    #pragma unroll
    for (int mi = 0; mi < 4; mi++) {
        const int m_off = wm * 64 + mi * 16 + mch_l;
        amoff[mi] = (((m_off >> 3) ^ (l & 7)) << 4);
    }
    const int brow_l = (l & 7) + ((l >> 4) & 1) * 8;
    const int bcol_l = (l >> 3) & 1;
    int bbase[4], bsw[4];
    #pragma unroll
    for (int jj = 0; jj < 4; jj++) {
        const int nrow = wn * 64 + jj * 16 + brow_l;
        bbase[jj] = nrow * 128;
        bsw[jj]   = nrow & 7;
    }

    b_stage_ld(sBst,        Bg, ldb, 0,  tid); cp_commit();
    b_stage_ld(sBst + BSTG, Bg, ldb, 64, tid); cp_commit();
    {
        float4 pf[4];
        a_ldg(pf, xbase, X, m0, 0, tid, 0, straddle);
        a_sts(sAbuf, pf, tid, 0);
        a_ldg(pf, xbase, X, m0, 0, tid, 1, straddle);
        a_sts(sAbuf, pf, tid, 1);
    }

    #pragma unroll 1
    for (int t = 0; t < T; t++) {
        cp_wait<1>();
        __syncthreads();

        float4 pf[4];
        const bool prodA = (t + 1 < T);
        if (prodA) a_ldg(pf, xbase, X, m0, (t + 1) * 64, tid, 0, straddle);
        if (t + 2 < T) b_stage_ld(sBst + ((t + 2) % 3) * BSTG, Bg, ldb, (t + 2) * 64, tid);
        cp_commit();

        const uint32_t sA = sAbuf + (t & 1) * ASTG;
        const uint32_t sAn = sAbuf + ((t + 1) & 1) * ASTG;
        const uint32_t sB = sBst + (t % 3) * BSTG;

        #pragma unroll
        for (int ks = 0; ks < 4; ks++) {
            uint32_t af[4][4];
            #pragma unroll
            for (int mi = 0; mi < 4; mi++)
                ldsm_x4_t(sA + arowb + ks * 4096 + amoff[mi],
                          af[mi][0], af[mi][1], af[mi][2], af[mi][3]);
            uint32_t bf[8][2];
            #pragma unroll
            for (int jj = 0; jj < 4; jj++)
                ldsm_x4(sB + bbase[jj] + (((ks * 2 + bcol_l) ^ bsw[jj]) * 16),
                        bf[jj * 2][0], bf[jj * 2][1], bf[jj * 2 + 1][0], bf[jj * 2 + 1][1]);
            #pragma unroll
            for (int i = 0; i < 4; i++)
                #pragma unroll
                for (int j = 0; j < 8; j++)
                    mma16816(acc[i][j], af[i], bf[j]);
            if (ks == 1 && prodA) {
                a_sts(sAn, pf, tid, 0);
                a_ldg(pf, xbase, X, m0, (t + 1) * 64, tid, 1, straddle);
            }
        }
        if (prodA) a_sts(sAn, pf, tid, 1);
    }

    const int r4 = l >> 2;
    const int c2 = (l & 3) * 2;
    #pragma unroll
    for (int i = 0; i < 4; i++) {
        const int row_a = m0 + wm * 64 + i * 16 + r4;
        #pragma unroll
        for (int h = 0; h < 2; h++) {
            const int row = row_a + h * 8;
            #pragma unroll
            for (int j = 0; j < 8; j++) {
                const int col = n0 + wn * 64 + j * 8 + c2;
                const __half2 hv = __floats2half2_rn(acc[i][j][h * 2],
                                                     acc[i][j][h * 2 + 1]);
                *(__half2*)(C + (size_t)row * ldc + col) = hv;
            }
        }
    }
}

// ---------------- GEMM2: 128x128 tile (2 CTAs/SM), fp16, channel-major out ----------------
#define STG2 32768   // per stage: A 128*128B + B 128*128B

__device__ __forceinline__ void stage_ld2(uint32_t sA, uint32_t sB,
    const __half* __restrict__ Ag, int lda,
    const __half* __restrict__ Bg, int ldb, int kt, int tid)
{
    #pragma unroll
    for (int i = 0; i < 4; i++) {
        const int idx = tid + i * 256;
        const int row = idx >> 3, j = idx & 7;
        const uint32_t off = (uint32_t)(row * 128 + ((j ^ (row & 7)) * 16));
        cp_async16(sA + off, Ag + (size_t)row * lda + kt + j * 8);
    }
    #pragma unroll
    for (int i = 0; i < 4; i++) {
        const int idx = tid + i * 256;
        const int row = idx >> 3, j = idx & 7;
        const uint32_t off = (uint32_t)(row * 128 + ((j ^ (row & 7)) * 16));
        cp_async16(sB + off, Bg + (size_t)row * ldb + kt + j * 8);
    }
}

template <int T>
__global__ __launch_bounds__(256) void hmma_gemm2(
    const __half* __restrict__ A, int lda,
    const __half* __restrict__ B, int ldb,
    const float* __restrict__ bias, float* __restrict__ C)
{
    extern __shared__ char dynraw[];
    const uint32_t smem = smem_u32(dynraw);
    const int tid = threadIdx.x;
    const int w = tid >> 5, l = tid & 31;
    const int wm = w >> 2, wn = w & 3;
    const int n0 = blockIdx.x * 128, m0 = blockIdx.y * 128;

    const __half* Ag = A + (size_t)m0 * lda;
    const __half* Bg = B + (size_t)n0 * ldb;

    float acc[4][4][4];
    #pragma unroll
    for (int i = 0; i < 4; i++)
        #pragma unroll
        for (int j = 0; j < 4; j++)
            #pragma unroll
            for (int c = 0; c < 4; c++) acc[i][j][c] = 0.f;

    const int arow_l = (l & 7) + ((l >> 3) & 1) * 8;
    const int acol_l = (l >> 4) & 1;
    const int brow_l = (l & 7) + ((l >> 4) & 1) * 8;
    const int bcol_l = (l >> 3) & 1;

    int abase[4], asw[4];
    #pragma unroll
    for (int i = 0; i < 4; i++) {
        const int mrow = wm * 64 + i * 16 + arow_l;
        abase[i] = mrow * 128;
        asw[i]   = mrow & 7;
    }
    int bbase[2], bsw[2];
    #pragma unroll
    for (int jj = 0; jj < 2; jj++) {
        const int nrow = wn * 32 + jj * 16 + brow_l;
        bbase[jj] = nrow * 128;
        bsw[jj]   = nrow & 7;
    }

    const int ks0 = ((w >> 2) & 1) << 1;

    stage_ld2(smem,        smem + 16384,        Ag, lda, Bg, ldb, 0,  tid); cp_commit();
    stage_ld2(smem + STG2, smem + STG2 + 16384, Ag, lda, Bg, ldb, 64, tid); cp_commit();

    #pragma unroll 1
    for (int t = 0; t < T; t++) {
        cp_wait<1>();
        __syncthreads();
        if (t + 2 < T) {
            const int s2 = (t + 2) % 3;
            stage_ld2(smem + s2 * STG2, smem + s2 * STG2 + 16384,
                      Ag, lda, Bg, ldb, (t + 2) * 64, tid);
        }
        cp_commit();

        const uint32_t sA = smem + (t % 3) * STG2;
        const uint32_t sB = sA + 16384;
        #pragma unroll
        for (int kss = 0; kss < 4; kss++) {
            const int ks = (kss + ks0) & 3;
            uint32_t af[4][4];
            #pragma unroll
            for (int i = 0; i < 4; i++)
                ldsm_x4(sA + abase[i] + (((ks * 2 + acol_l) ^ asw[i]) * 16),
                        af[i][0], af[i][1], af[i][2], af[i][3]);
            uint32_t bf[4][2];
            #pragma unroll
            for (int jj = 0; jj < 2; jj++)
                ldsm_x4(sB + bbase[jj] + (((ks * 2 + bcol_l) ^ bsw[jj]) * 16),
                        bf[jj * 2][0], bf[jj * 2][1], bf[jj * 2 + 1][0], bf[jj * 2 + 1][1]);
            #pragma unroll
            for (int i = 0; i < 4; i++)
                #pragma unroll
                for (int j = 0; j < 4; j++)
                    mma16816(acc[i][j], af[i], bf[j]);
        }
    }

    // Epilogue: channel-major out + bias
    const int r4 = l >> 2;
    const int c2 = (l & 3) * 2;
    #pragma unroll
    for (int i = 0; i < 4; i++) {
        const int row_a = m0 + wm * 64 + i * 16 + r4;
        #pragma unroll
        for (int h = 0; h < 2; h++) {
            const int row = row_a + h * 8;
            const float bv = bias[row];
            #pragma unroll
            for (int j = 0; j < 4; j++) {
                const int col = n0 + wn * 32 + j * 8 + c2;
                const int bb = col / HW;
                const int hw = col - bb * HW;
                float2 v = make_float2(acc[i][j][h * 2] + bv,
                                       acc[i][j][h * 2 + 1] + bv);
                *(float2*)(C + ((size_t)bb * DIMC + row) * HW + hw) = v;
            }
        }
    }
}

// ---------------- attention: warp per (pixel, head-pair), fp16 qkv (R11) ----------------
__device__ __forceinline__ float4 ld_h4(const __half* p) {
    const uint2 raw = *(const uint2*)p;
    const float2 a = __half22float2(*(const __half2*)&raw.x);
    const float2 b = __half22float2(*(const __half2*)&raw.y);
    return make_float4(a.x, a.y, b.x, b.y);
}

__global__ __launch_bounds__(256) void attn_kernel(
    const __half* __restrict__ qkvT, __half* __restrict__ aoT)
{
    const int w  = threadIdx.x >> 5;
    const int l  = threadIdx.x & 31;
    const int x  = blockIdx.x * 2 + (w >> 2);
    const int y  = blockIdx.y;
    const int b  = blockIdx.z;
    const int hp = w & 3;
    const int chb = hp * 128 + l * 4;

    const __half* base = qkvT + (size_t)(b * HW + y * IMG_W + x) * QKV_CH;
    const float4 q = ld_h4(base + chb);

    const bool interior = (x >= 1) && (x <= IMG_W - 2) && (y >= 1) && (y <= IMG_H - 2);

    float dots[9];
    if (interior) {
        #pragma unroll
        for (int r = 0; r < 3; r++) {
            const __half* krow = base + ((r - 1) * IMG_W - 1) * QKV_CH + INNER + chb;
            #pragma unroll
            for (int c = 0; c < 3; c++) {
                const float4 kk = ld_h4(krow + c * QKV_CH);
                dots[r * 3 + c] = fmaf(q.x, kk.x,
                                  fmaf(q.y, kk.y,
                                  fmaf(q.z, kk.z, q.w * kk.w)));
            }
        }
    } else {
        #pragma unroll
        for (int t = 0; t < 9; t++) {
            const int yy = y + t / 3 - 1;
            const int xx = x + t % 3 - 1;
            float d = 0.f;
            if (yy >= 0 && yy < IMG_H && xx >= 0 && xx < IMG_W) {
                const float4 kk = ld_h4(
                    qkvT + (size_t)(b * HW + yy * IMG_W + xx) * QKV_CH + INNER + chb);
                d = fmaf(q.x, kk.x, fmaf(q.y, kk.y, fmaf(q.z, kk.z, q.w * kk.w)));
            }
            dots[t] = d;
        }
    }

    #pragma unroll
    for (int off = 8; off; off >>= 1)
        #pragma unroll
        for (int t = 0; t < 9; t++)
            dots[t] += __shfl_xor_sync(0xFFFFFFFFu, dots[t], off);

    float m = -1e30f;
    #pragma unroll
    for (int t = 0; t < 9; t++) { dots[t] *= SCALE; m = fmaxf(m, dots[t]); }
    float wgt[9], s = 0.f;
    #pragma unroll
    for (int t = 0; t < 9; t++) { wgt[t] = __expf(dots[t] - m); s += wgt[t]; }
    const float inv = 1.f / s;
    #pragma unroll
    for (int t = 0; t < 9; t++) wgt[t] *= inv;

    float4 o = make_float4(0.f, 0.f, 0.f, 0.f);
    if (interior) {
        #pragma unroll
        for (int r = 0; r < 3; r++) {
            const __half* vrow = base + ((r - 1) * IMG_W - 1) * QKV_CH + 2 * INNER + chb;
            #pragma unroll
            for (int c = 0; c < 3; c++) {
                const float4 vv = ld_h4(vrow + c * QKV_CH);
                const float wt = wgt[r * 3 + c];
                o.x = fmaf(wt, vv.x, o.x);
                o.y = fmaf(wt, vv.y, o.y);
                o.z = fmaf(wt, vv.z, o.z);
                o.w = fmaf(wt, vv.w, o.w);
            }
        }
    } else {
        #pragma unroll
        for (int t = 0; t < 9; t++) {
            const int yy = y + t / 3 - 1;
            const int xx = x + t % 3 - 1;
            if (yy >= 0 && yy < IMG_H && xx >= 0 && xx < IMG_W) {
                const float4 vv = ld_h4(
                    qkvT + (size_t)(b * HW + yy * IMG_W + xx) * QKV_CH + 2 * INNER + chb);
                const float wt = wgt[t];
                o.x = fmaf(wt, vv.x, o.x);
                o.y = fmaf(wt, vv.y, o.y);
                o.z = fmaf(wt, vv.z, o.z);
                o.w = fmaf(wt, vv.w, o.w);
            }
        }
    }

    __half2 p0 = __floats2half2_rn(o.x, o.y);
    __half2 p1 = __floats2half2_rn(o.z, o.w);
    __half2* dst = (__half2*)(aoT + (size_t)(b * HW + y * IMG_W + x) * INNER + chb);
    dst[0] = p0;
    dst[1] = p1;
}

// ---------------- launch ----------------
extern "C" void kernel_launch(void* const* d_in, const int* in_sizes, int n_in,
                              void* d_out, int out_size)
{
    const float* x   = (const float*)d_in[0];
    const float* Wq  = (const float*)d_in[1];
    const float* Wkv = (const float*)d_in[2];
    const float* Wo  = (const float*)d_in[3];
    const float* bo  = (const float*)d_in[4];
    float* out = (float*)d_out;

    __half *wqkv, *wo, *qkvT, *aoT;
    cudaGetSymbolAddress((void**)&wqkv, g_wqkv);
    cudaGetSymbolAddress((void**)&wo,   g_wo);
    cudaGetSymbolAddress((void**)&qkvT, g_qkvT);
    cudaGetSymbolAddress((void**)&aoT,  g_aoT);

    const int g1_smem = 3 * BSTG + 2 * ASTG;   // 128 KB
    const int g2_smem = 3 * STG2;              // 96 KB (2 CTAs/SM)
    cudaFuncSetAttribute((const void*)hmma_gemm_xa<K1 / 64>,
                         cudaFuncAttributeMaxDynamicSharedMemorySize, g1_smem);
    cudaFuncSetAttribute((const void*)hmma_gemm2<K2 / 64>,
                         cudaFuncAttributeMaxDynamicSharedMemorySize, g2_smem);

    // 0) weight converts only (x transpose fused into GEMM1)
    weights_convert<<<QKV_CH + DIMC, 512>>>(Wq, Wkv, Wo, wqkv, wo);

    // 1) qkv projection: D[p][ch] fp16, M=12544, N=1536, K=384, A fused from x
    hmma_gemm_xa<K1 / 64><<<dim3(QKV_CH / 256, NPIX / 128), 256, g1_smem>>>(
        x, wqkv, DIMC, qkvT, QKV_CH);

    // 2) neighborhood attention (warp per pixel-head-pair, fp16 qkv)
    attn_kernel<<<dim3(IMG_W / 2, IMG_H, BATCH), 256>>>(qkvT, aoT);

    // 3) out projection: 128x128 tiles, D[ch][p] -> out + bias, K=512
    hmma_gemm2<K2 / 64><<<dim3(NPIX / 128, DIMC / 128), 256, g2_smem>>>(
        wo, K2, aoT, INNER, bo, out);
}